// round 11
// baseline (speedup 1.0000x reference)
#include <cuda_runtime.h>

#define W0 4096
#define OUTW 1024
#define MAXMIP 8

// Mip texel = 4B fixed point: r[0:11) g[11:22) b[22:32)  (values in [0,1]).
// Quad entry (16B, uint4): texels {(x,y),(x+1,y),(x,y+1),(x+1,y+1)} with wrap.
// Levels 2..8: 1,398,016 entries * 16B = ~22.4MB.
__device__ uint4 g_mq[1398016];

__constant__ int MIPQ_OFF[9] = {
    0, 0,
    0,          // level 2: 1024^2
    1048576,    // level 3:  512^2
    1310720,    // level 4:  256^2
    1376256,    // level 5:  128^2
    1392640,    // level 6:   64^2
    1396736,    // level 7:   32^2
    1397760     // level 8:   16^2
};

#define OFF_L2 0
#define OFF_L3 1048576
#define OFF_L4 1310720
#define OFF_L5 1376256
#define OFF_L6 1392640
#define OFF_L7 1396736
#define OFF_L8 1397760

__device__ __forceinline__ unsigned pack_rgb(float3 v) {
    unsigned r = (unsigned)__float2int_rn(__saturatef(v.x) * 2047.0f);
    unsigned g = (unsigned)__float2int_rn(__saturatef(v.y) * 2047.0f);
    unsigned b = (unsigned)__float2int_rn(__saturatef(v.z) * 1023.0f);
    return r | (g << 11) | (b << 22);
}

__device__ __forceinline__ float3 unpack_rgb(unsigned p) {
    return make_float3((float)(p & 2047u) * (1.0f / 2047.0f),
                       (float)((p >> 11) & 2047u) * (1.0f / 2047.0f),
                       (float)(p >> 22) * (1.0f / 1023.0f));
}

// Write texel (x,y) into the 4 quad entries that reference it (w = power of 2).
__device__ __forceinline__ void store_quad(unsigned* __restrict__ base, int w,
                                           int x, int y, float3 v) {
    unsigned p = pack_rgb(v);
    int xm = (x - 1) & (w - 1);
    int ym = (y - 1) & (w - 1);
    base[((size_t)y * w + x) * 4 + 0] = p;
    base[((size_t)y * w + xm) * 4 + 1] = p;
    base[((size_t)ym * w + x) * 4 + 2] = p;
    base[((size_t)ym * w + xm) * 4 + 3] = p;
}

__device__ __forceinline__ float3 f3avg(float3 a, float3 b, float3 c, float3 d) {
    return make_float3((a.x + b.x + c.x + d.x) * 0.25f,
                       (a.y + b.y + c.y + d.y) * 0.25f,
                       (a.z + b.z + c.z + d.z) * 0.25f);
}

__device__ __forceinline__ float3 quad_avg(uint4 q) {
    return f3avg(unpack_rgb(q.x), unpack_rgb(q.y), unpack_rgb(q.z), unpack_rgb(q.w));
}

__device__ __forceinline__ float4 f4avg4(float4 a, float4 b, float4 c, float4 d) {
    return make_float4((a.x + b.x + c.x + d.x) * 0.25f,
                       (a.y + b.y + c.y + d.y) * 0.25f,
                       (a.z + b.z + c.z + d.z) * 0.25f, 0.0f);
}

// Streaming (evict-first) 3x float4 load.
__device__ __forceinline__ void load12_cs(float* r, const float4* p) {
    float4 f0 = __ldcs(p), f1 = __ldcs(p + 1), f2 = __ldcs(p + 2);
    r[0] = f0.x; r[1]  = f0.y; r[2]  = f0.z; r[3]  = f0.w;
    r[4] = f1.x; r[5]  = f1.y; r[6]  = f1.z; r[7]  = f1.w;
    r[8] = f2.x; r[9]  = f2.y; r[10] = f2.z; r[11] = f2.w;
}

// Kernel A: base (packed fp32 rgb) -> level 2 only (quad writes).
__global__ __launch_bounds__(256) void vt_downA(const float* __restrict__ data) {
    const int w2 = W0 >> 2;              // 1024
    int i = blockIdx.x * blockDim.x + threadIdx.x;
    if (i >= w2 * w2) return;

    int x2 = i & (w2 - 1);
    int y2 = i >> 10;
    const int pitch4 = 3 * w2;
    const float4* s4 = reinterpret_cast<const float4*>(data)
                       + (size_t)4 * y2 * pitch4 + 3 * x2;

    float a[12], b[12];
    float3 l1[4];

#pragma unroll
    for (int half = 0; half < 2; half++) {
        load12_cs(a, s4 + (2 * half) * pitch4);
        load12_cs(b, s4 + (2 * half + 1) * pitch4);
#pragma unroll
        for (int dx = 0; dx < 2; dx++) {
            l1[2 * half + dx] = make_float3(
                (a[6 * dx + 0] + a[6 * dx + 3] + b[6 * dx + 0] + b[6 * dx + 3]) * 0.25f,
                (a[6 * dx + 1] + a[6 * dx + 4] + b[6 * dx + 1] + b[6 * dx + 4]) * 0.25f,
                (a[6 * dx + 2] + a[6 * dx + 5] + b[6 * dx + 2] + b[6 * dx + 5]) * 0.25f);
        }
    }

    float3 l2 = f3avg(l1[0], l1[1], l1[2], l1[3]);
    store_quad(reinterpret_cast<unsigned*>(g_mq + OFF_L2), 1024, x2, y2, l2);
}

// Kernel B: level 2 -> levels 3..8 in one kernel.
__global__ __launch_bounds__(256) void vt_downB() {
    __shared__ float4 s4[256];
    __shared__ float4 s5[64];
    __shared__ float4 s6[16];
    __shared__ float4 s7[4];

    const uint4* __restrict__ L2t = g_mq + OFF_L2;
    unsigned* __restrict__ L3 = reinterpret_cast<unsigned*>(g_mq + OFF_L3);
    unsigned* __restrict__ L4 = reinterpret_cast<unsigned*>(g_mq + OFF_L4);
    unsigned* __restrict__ L5 = reinterpret_cast<unsigned*>(g_mq + OFF_L5);
    unsigned* __restrict__ L6 = reinterpret_cast<unsigned*>(g_mq + OFF_L6);
    unsigned* __restrict__ L7 = reinterpret_cast<unsigned*>(g_mq + OFF_L7);
    unsigned* __restrict__ L8 = reinterpret_cast<unsigned*>(g_mq + OFF_L8);

    int t = threadIdx.x;
    int bx = blockIdx.x, by = blockIdx.y;
    int tx = t & 15, ty = t >> 4;

    {
        int x0 = 64 * bx + 4 * tx;
        int y0 = 64 * by + 4 * ty;
        const uint4* src = L2t + (size_t)y0 * 1024 + x0;

        float3 l3[4];
        l3[0] = quad_avg(src[0]);
        l3[1] = quad_avg(src[2]);
        l3[2] = quad_avg(src[(size_t)2 * 1024]);
        l3[3] = quad_avg(src[(size_t)2 * 1024 + 2]);

        int x3 = 32 * bx + 2 * tx;
        int y3 = 32 * by + 2 * ty;
        store_quad(L3, 512, x3,     y3,     l3[0]);
        store_quad(L3, 512, x3 + 1, y3,     l3[1]);
        store_quad(L3, 512, x3,     y3 + 1, l3[2]);
        store_quad(L3, 512, x3 + 1, y3 + 1, l3[3]);

        float3 l4 = f3avg(l3[0], l3[1], l3[2], l3[3]);
        store_quad(L4, 256, 16 * bx + tx, 16 * by + ty, l4);
        s4[ty * 16 + tx] = make_float4(l4.x, l4.y, l4.z, 0.0f);
    }
    __syncthreads();

    if (t < 64) {
        int x = t & 7, y = t >> 3;
        float4 v = f4avg4(s4[(2 * y) * 16 + 2 * x],     s4[(2 * y) * 16 + 2 * x + 1],
                          s4[(2 * y + 1) * 16 + 2 * x], s4[(2 * y + 1) * 16 + 2 * x + 1]);
        store_quad(L5, 128, 8 * bx + x, 8 * by + y, make_float3(v.x, v.y, v.z));
        s5[y * 8 + x] = v;
    }
    __syncthreads();

    if (t < 16) {
        int x = t & 3, y = t >> 2;
        float4 v = f4avg4(s5[(2 * y) * 8 + 2 * x],     s5[(2 * y) * 8 + 2 * x + 1],
                          s5[(2 * y + 1) * 8 + 2 * x], s5[(2 * y + 1) * 8 + 2 * x + 1]);
        store_quad(L6, 64, 4 * bx + x, 4 * by + y, make_float3(v.x, v.y, v.z));
        s6[y * 4 + x] = v;
    }
    __syncthreads();

    if (t < 4) {
        int x = t & 1, y = t >> 1;
        float4 v = f4avg4(s6[(2 * y) * 4 + 2 * x],     s6[(2 * y) * 4 + 2 * x + 1],
                          s6[(2 * y + 1) * 4 + 2 * x], s6[(2 * y + 1) * 4 + 2 * x + 1]);
        store_quad(L7, 32, 2 * bx + x, 2 * by + y, make_float3(v.x, v.y, v.z));
        s7[y * 2 + x] = v;
    }
    __syncthreads();

    if (t == 0) {
        float4 a = s7[0], b = s7[1], c = s7[2], d = s7[3];
        store_quad(L8, 16, bx, by,
                   make_float3((a.x + b.x + c.x + d.x) * 0.25f,
                               (a.y + b.y + c.y + d.y) * 0.25f,
                               (a.z + b.z + c.z + d.z) * 0.25f));
    }
}

// ---------- sampling helpers ----------

__device__ __forceinline__ void wrap_setup(float u, float v, int w,
                                           int& x0, int& y0, int& x1, int& y1,
                                           float& fx, float& fy) {
    float x = u * (float)w - 0.5f;
    float y = v * (float)w - 0.5f;
    float x0f = floorf(x);
    float y0f = floorf(y);
    fx = x - x0f;
    fy = y - y0f;
    x0 = (int)x0f;
    y0 = (int)y0f;
    if (x0 < 0) x0 += w;
    if (y0 < 0) y0 += w;
    x1 = x0 + 1; if (x1 == w) x1 = 0;
    y1 = y0 + 1; if (y1 == w) y1 = 0;
}

__device__ __forceinline__ void quad_blend(uint4 e, float fx, float fy, float rgb[3]) {
    float3 t00 = unpack_rgb(e.x), t01 = unpack_rgb(e.y);
    float3 t10 = unpack_rgb(e.z), t11 = unpack_rgb(e.w);
    float w00 = (1.0f - fx) * (1.0f - fy);
    float w01 = fx * (1.0f - fy);
    float w10 = (1.0f - fx) * fy;
    float w11 = fx * fy;
    rgb[0] = t00.x * w00 + t01.x * w01 + t10.x * w10 + t11.x * w11;
    rgb[1] = t00.y * w00 + t01.y * w01 + t10.y * w10 + t11.y * w11;
    rgb[2] = t00.z * w00 + t01.z * w01 + t10.z * w10 + t11.z * w11;
}

// Quad entry address for (u,v) at level lvl (>=2). fx/fy out.
__device__ __forceinline__ const uint4* quad_addr(int lvl, float u, float v,
                                                  float& fx, float& fy) {
    int w = W0 >> lvl;
    float x = u * (float)w - 0.5f;
    float y = v * (float)w - 0.5f;
    float xf = floorf(x), yf = floorf(y);
    int xi = (int)xf, yi = (int)yf;
    if (xi < 0) xi += w;
    if (yi < 0) yi += w;
    fx = x - xf; fy = y - yf;
    return g_mq + MIPQ_OFF[lvl] + (size_t)yi * w + xi;
}

// Exact fp32 bilinear on base (level 0). Rare path.
__device__ __forceinline__ void vt_bilinear0(const float* __restrict__ tex,
                                             float u, float v, float rgb[3]) {
    int x0, y0, x1, y1; float fx, fy;
    wrap_setup(u, v, W0, x0, y0, x1, y1, fx, fy);

    const float* p00 = tex + ((size_t)y0 * W0 + x0) * 3;
    const float* p01 = tex + ((size_t)y0 * W0 + x1) * 3;
    const float* p10 = tex + ((size_t)y1 * W0 + x0) * 3;
    const float* p11 = tex + ((size_t)y1 * W0 + x1) * 3;

    float w00 = (1.0f - fx) * (1.0f - fy);
    float w01 = fx * (1.0f - fy);
    float w10 = (1.0f - fx) * fy;
    float w11 = fx * fy;

#pragma unroll
    for (int c = 0; c < 3; c++)
        rgb[c] = p00[c] * w00 + p01[c] * w01 + p10[c] * w10 + p11[c] * w11;
}

__device__ __forceinline__ float3 l1_texel(const float* __restrict__ base,
                                           int lx, int ly) {
    const float2* r0 = reinterpret_cast<const float2*>(
        base + ((size_t)(2 * ly) * W0 + 2 * lx) * 3);
    const float2* r1 = reinterpret_cast<const float2*>(
        base + ((size_t)(2 * ly + 1) * W0 + 2 * lx) * 3);
    float2 a0 = r0[0], a1 = r0[1], a2 = r0[2];
    float2 b0 = r1[0], b1 = r1[1], b2 = r1[2];
    return make_float3((a0.x + a1.y + b0.x + b1.y) * 0.25f,
                       (a0.y + a2.x + b0.y + b2.x) * 0.25f,
                       (a1.x + a2.y + b1.x + b2.y) * 0.25f);
}

__device__ __forceinline__ void vt_bilinear_l1(const float* __restrict__ tex,
                                               float u, float v, float rgb[3]) {
    const int w1 = W0 >> 1;
    int x0, y0, x1, y1; float fx, fy;
    wrap_setup(u, v, w1, x0, y0, x1, y1, fx, fy);

    float3 t00 = l1_texel(tex, x0, y0);
    float3 t01 = l1_texel(tex, x1, y0);
    float3 t10 = l1_texel(tex, x0, y1);
    float3 t11 = l1_texel(tex, x1, y1);

    float w00 = (1.0f - fx) * (1.0f - fy);
    float w01 = fx * (1.0f - fy);
    float w10 = (1.0f - fx) * fy;
    float w11 = fx * fy;

    rgb[0] = t00.x * w00 + t01.x * w01 + t10.x * w10 + t11.x * w11;
    rgb[1] = t00.y * w00 + t01.y * w01 + t10.y * w10 + t11.y * w11;
    rgb[2] = t00.z * w00 + t01.z * w01 + t10.z * w10 + t11.z * w11;
}

// Rare path (l0 < 2): exact fp32 from base.
__device__ __noinline__ void sample_rare(const float* __restrict__ data,
                                         float u, float v, int l0, float frac,
                                         float rgb[3]) {
    float a[3], b[3];
    if (l0 == 1) {
        vt_bilinear_l1(data, u, v, a);
        float fx, fy;
        const uint4* e = quad_addr(2, u, v, fx, fy);
        quad_blend(*e, fx, fy, b);
    } else {
        vt_bilinear0(data, u, v, a);
        vt_bilinear_l1(data, u, v, b);
    }
    float w0 = 1.0f - frac;
    rgb[0] = a[0] * w0 + b[0] * frac;
    rgb[1] = a[1] * w0 + b[1] * frac;
    rgb[2] = a[2] * w0 + b[2] * frac;
}

// ---------- cp.async helpers ----------
__device__ __forceinline__ void cp_async16(unsigned smem_addr, const void* gptr) {
    asm volatile("cp.async.cg.shared.global [%0], [%1], 16;\n"
                 :: "r"(smem_addr), "l"(gptr) : "memory");
}
__device__ __forceinline__ void cp_async_commit() {
    asm volatile("cp.async.commit_group;\n" ::: "memory");
}
__device__ __forceinline__ void cp_async_wait0() {
    asm volatile("cp.async.wait_group 0;\n" ::: "memory");
}

// Four pixels per thread; 8 gathers staged in smem via cp.async (regs stay low).
__global__ __launch_bounds__(256) void vt_sample(const float* __restrict__ data,
                          const float4* __restrict__ texc2,
                          const float4* __restrict__ deriv,
                          float4* __restrict__ out4) {
    __shared__ uint4 sbuf[8 * 256];      // [slot][tid], 32KB

    int tid = threadIdx.x;
    int p = blockIdx.x * blockDim.x + tid;
    const int ngroups = OUTW * OUTW / 4;
    if (p >= ngroups) return;

    unsigned sb = (unsigned)__cvta_generic_to_shared(&sbuf[tid]);
    const unsigned slot_stride = 256 * 16;   // bytes between slots for this tid

    float4 uvA = __ldcs(texc2 + 2 * p);
    float4 uvB = __ldcs(texc2 + 2 * p + 1);
    float u[4] = { uvA.x, uvA.z, uvB.x, uvB.z };
    float v[4] = { uvA.y, uvA.w, uvB.y, uvB.w };

    float frac[4];
    int l0[4];
    bool rare = false;
    float fx0[4], fy0[4], fx1[4], fy1[4];

#pragma unroll
    for (int k = 0; k < 4; k++) {
        float4 dd = __ldcs(deriv + 4 * p + k);
        float dudx = dd.x * (float)W0;
        float dvdx = dd.y * (float)W0;
        float dudy = dd.z * (float)W0;
        float dvdy = dd.w * (float)W0;
        float rho2 = fmaxf(dudx * dudx + dvdx * dvdx, dudy * dudy + dvdy * dvdy);
        float lod = 0.5f * __log2f(fmaxf(rho2, 1e-20f));
        lod = fminf(fmaxf(lod, 0.0f), (float)MAXMIP);
        int l = (int)lod;
        if (l > MAXMIP) l = MAXMIP;
        l0[k] = l;
        frac[k] = lod - (float)l;
        rare |= (l < 2);

        // clamp async fetch levels to [2, MAXMIP] (rare pixels recomputed later)
        int la = (l < 2) ? 2 : l;
        int lb = (l + 1 > MAXMIP) ? MAXMIP : ((l + 1 < 2) ? 2 : l + 1);

        const uint4* a0 = quad_addr(la, u[k], v[k], fx0[k], fy0[k]);
        const uint4* a1 = quad_addr(lb, u[k], v[k], fx1[k], fy1[k]);
        cp_async16(sb + (2 * k + 0) * slot_stride, a0);
        cp_async16(sb + (2 * k + 1) * slot_stride, a1);
    }
    cp_async_commit();
    cp_async_wait0();

    float r[4][3];
#pragma unroll
    for (int k = 0; k < 4; k++) {
        uint4 e0 = sbuf[(2 * k + 0) * 256 + tid];
        uint4 e1 = sbuf[(2 * k + 1) * 256 + tid];
        float a[3], b[3];
        quad_blend(e0, fx0[k], fy0[k], a);
        quad_blend(e1, fx1[k], fy1[k], b);
        float w0 = 1.0f - frac[k];
        r[k][0] = a[0] * w0 + b[0] * frac[k];
        r[k][1] = a[1] * w0 + b[1] * frac[k];
        r[k][2] = a[2] * w0 + b[2] * frac[k];
    }

    if (rare) {
#pragma unroll
        for (int k = 0; k < 4; k++)
            if (l0[k] < 2)
                sample_rare(data, u[k], v[k], l0[k], frac[k], r[k]);
    }

    float4* o = out4 + (size_t)3 * p;
    o[0] = make_float4(r[0][0], r[0][1], r[0][2], r[1][0]);
    o[1] = make_float4(r[1][1], r[1][2], r[2][0], r[2][1]);
    o[2] = make_float4(r[2][2], r[3][0], r[3][1], r[3][2]);
}

extern "C" void kernel_launch(void* const* d_in, const int* in_sizes, int n_in,
                              void* d_out, int out_size) {
    const float* data  = (const float*)d_in[0];   // [1,4096,4096,3]
    const float4* texc2 = (const float4*)d_in[1]; // [1,1024,1024,2] as float4 pairs
    const float4* deriv = (const float4*)d_in[2]; // [1,1024,1024,4]
    float4* out4 = (float4*)d_out;                // [1,1024,1024,3] as float4

    (void)in_sizes; (void)n_in; (void)out_size;

    vt_downA<<<4096, 256>>>(data);
    {
        dim3 grid(16, 16);
        vt_downB<<<grid, 256>>>();
    }
    vt_sample<<<1024, 256>>>(data, texc2, deriv, out4);
}

// round 14
// speedup vs baseline: 1.0594x; 1.0594x over previous
#include <cuda_runtime.h>

#define W0 4096
#define OUTW 1024
#define MAXMIP 8

// Mip texel = 4B fixed point: r[0:11) g[11:22) b[22:32)  (values in [0,1]).
// Quad entry (16B, uint4): texels {(x,y),(x+1,y),(x,y+1),(x+1,y+1)} with wrap.
// Levels 2..8: 1,398,016 entries * 16B = ~22.4MB.
__device__ uint4 g_mq[1398016];

__constant__ int MIPQ_OFF[9] = {
    0, 0,
    0,          // level 2: 1024^2
    1048576,    // level 3:  512^2
    1310720,    // level 4:  256^2
    1376256,    // level 5:  128^2
    1392640,    // level 6:   64^2
    1396736,    // level 7:   32^2
    1397760     // level 8:   16^2
};

#define OFF_L2 0
#define OFF_L3 1048576
#define OFF_L4 1310720
#define OFF_L5 1376256
#define OFF_L6 1392640
#define OFF_L7 1396736
#define OFF_L8 1397760

__device__ __forceinline__ unsigned pack_rgb(float3 v) {
    unsigned r = (unsigned)__float2int_rn(__saturatef(v.x) * 2047.0f);
    unsigned g = (unsigned)__float2int_rn(__saturatef(v.y) * 2047.0f);
    unsigned b = (unsigned)__float2int_rn(__saturatef(v.z) * 1023.0f);
    return r | (g << 11) | (b << 22);
}

__device__ __forceinline__ float3 unpack_rgb(unsigned p) {
    return make_float3((float)(p & 2047u) * (1.0f / 2047.0f),
                       (float)((p >> 11) & 2047u) * (1.0f / 2047.0f),
                       (float)(p >> 22) * (1.0f / 1023.0f));
}

// Write texel (x,y) into the 4 quad entries that reference it (w = power of 2).
__device__ __forceinline__ void store_quad(unsigned* __restrict__ base, int w,
                                           int x, int y, float3 v) {
    unsigned p = pack_rgb(v);
    int xm = (x - 1) & (w - 1);
    int ym = (y - 1) & (w - 1);
    base[((size_t)y * w + x) * 4 + 0] = p;
    base[((size_t)y * w + xm) * 4 + 1] = p;
    base[((size_t)ym * w + x) * 4 + 2] = p;
    base[((size_t)ym * w + xm) * 4 + 3] = p;
}

__device__ __forceinline__ float3 f3avg(float3 a, float3 b, float3 c, float3 d) {
    return make_float3((a.x + b.x + c.x + d.x) * 0.25f,
                       (a.y + b.y + c.y + d.y) * 0.25f,
                       (a.z + b.z + c.z + d.z) * 0.25f);
}

__device__ __forceinline__ float3 quad_avg(uint4 q) {
    return f3avg(unpack_rgb(q.x), unpack_rgb(q.y), unpack_rgb(q.z), unpack_rgb(q.w));
}

__device__ __forceinline__ float4 f4avg4(float4 a, float4 b, float4 c, float4 d) {
    return make_float4((a.x + b.x + c.x + d.x) * 0.25f,
                       (a.y + b.y + c.y + d.y) * 0.25f,
                       (a.z + b.z + c.z + d.z) * 0.25f, 0.0f);
}

// Streaming (evict-first) 3x float4 load.
__device__ __forceinline__ void load12_cs(float* r, const float4* p) {
    float4 f0 = __ldcs(p), f1 = __ldcs(p + 1), f2 = __ldcs(p + 2);
    r[0] = f0.x; r[1]  = f0.y; r[2]  = f0.z; r[3]  = f0.w;
    r[4] = f1.x; r[5]  = f1.y; r[6]  = f1.z; r[7]  = f1.w;
    r[8] = f2.x; r[9]  = f2.y; r[10] = f2.z; r[11] = f2.w;
}

// Kernel A: base (packed fp32 rgb) -> level 2 only (quad writes).
__global__ __launch_bounds__(256) void vt_downA(const float* __restrict__ data) {
    const int w2 = W0 >> 2;              // 1024
    int i = blockIdx.x * blockDim.x + threadIdx.x;
    if (i >= w2 * w2) return;

    int x2 = i & (w2 - 1);
    int y2 = i >> 10;
    const int pitch4 = 3 * w2;
    const float4* s4 = reinterpret_cast<const float4*>(data)
                       + (size_t)4 * y2 * pitch4 + 3 * x2;

    float a[12], b[12];
    float3 l1[4];

#pragma unroll
    for (int half = 0; half < 2; half++) {
        load12_cs(a, s4 + (2 * half) * pitch4);
        load12_cs(b, s4 + (2 * half + 1) * pitch4);
#pragma unroll
        for (int dx = 0; dx < 2; dx++) {
            l1[2 * half + dx] = make_float3(
                (a[6 * dx + 0] + a[6 * dx + 3] + b[6 * dx + 0] + b[6 * dx + 3]) * 0.25f,
                (a[6 * dx + 1] + a[6 * dx + 4] + b[6 * dx + 1] + b[6 * dx + 4]) * 0.25f,
                (a[6 * dx + 2] + a[6 * dx + 5] + b[6 * dx + 2] + b[6 * dx + 5]) * 0.25f);
        }
    }

    float3 l2 = f3avg(l1[0], l1[1], l1[2], l1[3]);
    store_quad(reinterpret_cast<unsigned*>(g_mq + OFF_L2), 1024, x2, y2, l2);
}

// Kernel B: level 2 -> levels 3..8 in one kernel.
__global__ __launch_bounds__(256) void vt_downB() {
    __shared__ float4 s4[256];
    __shared__ float4 s5[64];
    __shared__ float4 s6[16];
    __shared__ float4 s7[4];

    const uint4* __restrict__ L2t = g_mq + OFF_L2;
    unsigned* __restrict__ L3 = reinterpret_cast<unsigned*>(g_mq + OFF_L3);
    unsigned* __restrict__ L4 = reinterpret_cast<unsigned*>(g_mq + OFF_L4);
    unsigned* __restrict__ L5 = reinterpret_cast<unsigned*>(g_mq + OFF_L5);
    unsigned* __restrict__ L6 = reinterpret_cast<unsigned*>(g_mq + OFF_L6);
    unsigned* __restrict__ L7 = reinterpret_cast<unsigned*>(g_mq + OFF_L7);
    unsigned* __restrict__ L8 = reinterpret_cast<unsigned*>(g_mq + OFF_L8);

    int t = threadIdx.x;
    int bx = blockIdx.x, by = blockIdx.y;
    int tx = t & 15, ty = t >> 4;

    {
        int x0 = 64 * bx + 4 * tx;
        int y0 = 64 * by + 4 * ty;
        const uint4* src = L2t + (size_t)y0 * 1024 + x0;

        float3 l3[4];
        l3[0] = quad_avg(src[0]);
        l3[1] = quad_avg(src[2]);
        l3[2] = quad_avg(src[(size_t)2 * 1024]);
        l3[3] = quad_avg(src[(size_t)2 * 1024 + 2]);

        int x3 = 32 * bx + 2 * tx;
        int y3 = 32 * by + 2 * ty;
        store_quad(L3, 512, x3,     y3,     l3[0]);
        store_quad(L3, 512, x3 + 1, y3,     l3[1]);
        store_quad(L3, 512, x3,     y3 + 1, l3[2]);
        store_quad(L3, 512, x3 + 1, y3 + 1, l3[3]);

        float3 l4 = f3avg(l3[0], l3[1], l3[2], l3[3]);
        store_quad(L4, 256, 16 * bx + tx, 16 * by + ty, l4);
        s4[ty * 16 + tx] = make_float4(l4.x, l4.y, l4.z, 0.0f);
    }
    __syncthreads();

    if (t < 64) {
        int x = t & 7, y = t >> 3;
        float4 v = f4avg4(s4[(2 * y) * 16 + 2 * x],     s4[(2 * y) * 16 + 2 * x + 1],
                          s4[(2 * y + 1) * 16 + 2 * x], s4[(2 * y + 1) * 16 + 2 * x + 1]);
        store_quad(L5, 128, 8 * bx + x, 8 * by + y, make_float3(v.x, v.y, v.z));
        s5[y * 8 + x] = v;
    }
    __syncthreads();

    if (t < 16) {
        int x = t & 3, y = t >> 2;
        float4 v = f4avg4(s5[(2 * y) * 8 + 2 * x],     s5[(2 * y) * 8 + 2 * x + 1],
                          s5[(2 * y + 1) * 8 + 2 * x], s5[(2 * y + 1) * 8 + 2 * x + 1]);
        store_quad(L6, 64, 4 * bx + x, 4 * by + y, make_float3(v.x, v.y, v.z));
        s6[y * 4 + x] = v;
    }
    __syncthreads();

    if (t < 4) {
        int x = t & 1, y = t >> 1;
        float4 v = f4avg4(s6[(2 * y) * 4 + 2 * x],     s6[(2 * y) * 4 + 2 * x + 1],
                          s6[(2 * y + 1) * 4 + 2 * x], s6[(2 * y + 1) * 4 + 2 * x + 1]);
        store_quad(L7, 32, 2 * bx + x, 2 * by + y, make_float3(v.x, v.y, v.z));
        s7[y * 2 + x] = v;
    }
    __syncthreads();

    if (t == 0) {
        float4 a = s7[0], b = s7[1], c = s7[2], d = s7[3];
        store_quad(L8, 16, bx, by,
                   make_float3((a.x + b.x + c.x + d.x) * 0.25f,
                               (a.y + b.y + c.y + d.y) * 0.25f,
                               (a.z + b.z + c.z + d.z) * 0.25f));
    }
}

// ---------- sampling helpers ----------

__device__ __forceinline__ void wrap_setup(float u, float v, int w,
                                           int& x0, int& y0, int& x1, int& y1,
                                           float& fx, float& fy) {
    float x = u * (float)w - 0.5f;
    float y = v * (float)w - 0.5f;
    float x0f = floorf(x);
    float y0f = floorf(y);
    fx = x - x0f;
    fy = y - y0f;
    x0 = (int)x0f;
    y0 = (int)y0f;
    if (x0 < 0) x0 += w;
    if (y0 < 0) y0 += w;
    x1 = x0 + 1; if (x1 == w) x1 = 0;
    y1 = y0 + 1; if (y1 == w) y1 = 0;
}

__device__ __forceinline__ void quad_blend(uint4 e, float fx, float fy, float rgb[3]) {
    float3 t00 = unpack_rgb(e.x), t01 = unpack_rgb(e.y);
    float3 t10 = unpack_rgb(e.z), t11 = unpack_rgb(e.w);
    float w00 = (1.0f - fx) * (1.0f - fy);
    float w01 = fx * (1.0f - fy);
    float w10 = (1.0f - fx) * fy;
    float w11 = fx * fy;
    rgb[0] = t00.x * w00 + t01.x * w01 + t10.x * w10 + t11.x * w11;
    rgb[1] = t00.y * w00 + t01.y * w01 + t10.y * w10 + t11.y * w11;
    rgb[2] = t00.z * w00 + t01.z * w01 + t10.z * w10 + t11.z * w11;
}

// Quad entry address for (u,v) at level lvl (>=2). fx/fy out.
__device__ __forceinline__ const uint4* quad_addr(int lvl, float u, float v,
                                                  float& fx, float& fy) {
    int w = W0 >> lvl;
    float x = u * (float)w - 0.5f;
    float y = v * (float)w - 0.5f;
    float xf = floorf(x), yf = floorf(y);
    int xi = (int)xf, yi = (int)yf;
    if (xi < 0) xi += w;
    if (yi < 0) yi += w;
    fx = x - xf; fy = y - yf;
    return g_mq + MIPQ_OFF[lvl] + (size_t)yi * w + xi;
}

// Exact fp32 bilinear on base (level 0). Rare path.
__device__ __forceinline__ void vt_bilinear0(const float* __restrict__ tex,
                                             float u, float v, float rgb[3]) {
    int x0, y0, x1, y1; float fx, fy;
    wrap_setup(u, v, W0, x0, y0, x1, y1, fx, fy);

    const float* p00 = tex + ((size_t)y0 * W0 + x0) * 3;
    const float* p01 = tex + ((size_t)y0 * W0 + x1) * 3;
    const float* p10 = tex + ((size_t)y1 * W0 + x0) * 3;
    const float* p11 = tex + ((size_t)y1 * W0 + x1) * 3;

    float w00 = (1.0f - fx) * (1.0f - fy);
    float w01 = fx * (1.0f - fy);
    float w10 = (1.0f - fx) * fy;
    float w11 = fx * fy;

#pragma unroll
    for (int c = 0; c < 3; c++)
        rgb[c] = p00[c] * w00 + p01[c] * w01 + p10[c] * w10 + p11[c] * w11;
}

__device__ __forceinline__ float3 l1_texel(const float* __restrict__ base,
                                           int lx, int ly) {
    const float2* r0 = reinterpret_cast<const float2*>(
        base + ((size_t)(2 * ly) * W0 + 2 * lx) * 3);
    const float2* r1 = reinterpret_cast<const float2*>(
        base + ((size_t)(2 * ly + 1) * W0 + 2 * lx) * 3);
    float2 a0 = r0[0], a1 = r0[1], a2 = r0[2];
    float2 b0 = r1[0], b1 = r1[1], b2 = r1[2];
    return make_float3((a0.x + a1.y + b0.x + b1.y) * 0.25f,
                       (a0.y + a2.x + b0.y + b2.x) * 0.25f,
                       (a1.x + a2.y + b1.x + b2.y) * 0.25f);
}

__device__ __forceinline__ void vt_bilinear_l1(const float* __restrict__ tex,
                                               float u, float v, float rgb[3]) {
    const int w1 = W0 >> 1;
    int x0, y0, x1, y1; float fx, fy;
    wrap_setup(u, v, w1, x0, y0, x1, y1, fx, fy);

    float3 t00 = l1_texel(tex, x0, y0);
    float3 t01 = l1_texel(tex, x1, y0);
    float3 t10 = l1_texel(tex, x0, y1);
    float3 t11 = l1_texel(tex, x1, y1);

    float w00 = (1.0f - fx) * (1.0f - fy);
    float w01 = fx * (1.0f - fy);
    float w10 = (1.0f - fx) * fy;
    float w11 = fx * fy;

    rgb[0] = t00.x * w00 + t01.x * w01 + t10.x * w10 + t11.x * w11;
    rgb[1] = t00.y * w00 + t01.y * w01 + t10.y * w10 + t11.y * w11;
    rgb[2] = t00.z * w00 + t01.z * w01 + t10.z * w10 + t11.z * w11;
}

// Rare path (l0 < 2): exact fp32 from base.
__device__ __noinline__ void sample_rare(const float* __restrict__ data,
                                         float u, float v, int l0, float frac,
                                         float rgb[3]) {
    float a[3], b[3];
    if (l0 == 1) {
        vt_bilinear_l1(data, u, v, a);
        float fx, fy;
        const uint4* e = quad_addr(2, u, v, fx, fy);
        quad_blend(*e, fx, fy, b);
    } else {
        vt_bilinear0(data, u, v, a);
        vt_bilinear_l1(data, u, v, b);
    }
    float w0 = 1.0f - frac;
    rgb[0] = a[0] * w0 + b[0] * frac;
    rgb[1] = a[1] * w0 + b[1] * frac;
    rgb[2] = a[2] * w0 + b[2] * frac;
}

// Two pixels per thread; all 4 gather loads issued before any blending.
__global__ __launch_bounds__(256) void vt_sample(const float* __restrict__ data,
                          const float4* __restrict__ texc2,
                          const float4* __restrict__ deriv,
                          float* __restrict__ out) {
    int p = blockIdx.x * blockDim.x + threadIdx.x;
    const int npairs = OUTW * OUTW / 2;
    if (p >= npairs) return;

    float4 uvs = __ldcs(texc2 + p);        // (u0,v0,u1,v1)
    float4 dA = __ldcs(deriv + 2 * p);
    float4 dB = __ldcs(deriv + 2 * p + 1);

    float u[2] = { uvs.x, uvs.z };
    float v[2] = { uvs.y, uvs.w };
    float4 dd[2] = { dA, dB };

    float frac[2];
    int l0[2], l1v[2];
    bool rare = false;
#pragma unroll
    for (int k = 0; k < 2; k++) {
        float dudx = dd[k].x * (float)W0;
        float dvdx = dd[k].y * (float)W0;
        float dudy = dd[k].z * (float)W0;
        float dvdy = dd[k].w * (float)W0;
        float rho2 = fmaxf(dudx * dudx + dvdx * dvdx, dudy * dudy + dvdy * dvdy);
        float lod = 0.5f * __log2f(fmaxf(rho2, 1e-20f));
        lod = fminf(fmaxf(lod, 0.0f), (float)MAXMIP);
        int l = (int)lod;
        if (l > MAXMIP) l = MAXMIP;
        l0[k] = l;
        frac[k] = lod - (float)l;
        l1v[k] = (l < MAXMIP) ? (l + 1) : MAXMIP;
        rare |= (l < 2);
    }

    float r[2][3];

    if (!rare) {
        // Issue all 4 LDG.128 before consuming any.
        float fx0[2], fy0[2], fx1[2], fy1[2];
        const uint4* a0 = quad_addr(l0[0],  u[0], v[0], fx0[0], fy0[0]);
        const uint4* a1 = quad_addr(l1v[0], u[0], v[0], fx1[0], fy1[0]);
        const uint4* b0 = quad_addr(l0[1],  u[1], v[1], fx0[1], fy0[1]);
        const uint4* b1 = quad_addr(l1v[1], u[1], v[1], fx1[1], fy1[1]);
        uint4 eA0 = *a0;
        uint4 eA1 = *a1;
        uint4 eB0 = *b0;
        uint4 eB1 = *b1;

        float a[3], b[3];
        quad_blend(eA0, fx0[0], fy0[0], a);
        quad_blend(eA1, fx1[0], fy1[0], b);
        float w0 = 1.0f - frac[0];
        r[0][0] = a[0] * w0 + b[0] * frac[0];
        r[0][1] = a[1] * w0 + b[1] * frac[0];
        r[0][2] = a[2] * w0 + b[2] * frac[0];

        quad_blend(eB0, fx0[1], fy0[1], a);
        quad_blend(eB1, fx1[1], fy1[1], b);
        float w1 = 1.0f - frac[1];
        r[1][0] = a[0] * w1 + b[0] * frac[1];
        r[1][1] = a[1] * w1 + b[1] * frac[1];
        r[1][2] = a[2] * w1 + b[2] * frac[1];
    } else {
#pragma unroll
        for (int k = 0; k < 2; k++) {
            if (l0[k] >= 2) {
                float fxa, fya, fxb, fyb;
                const uint4* qa = quad_addr(l0[k],  u[k], v[k], fxa, fya);
                const uint4* qb = quad_addr(l1v[k], u[k], v[k], fxb, fyb);
                uint4 ea = *qa;
                uint4 eb = *qb;
                float a[3], b[3];
                quad_blend(ea, fxa, fya, a);
                quad_blend(eb, fxb, fyb, b);
                float w0 = 1.0f - frac[k];
                r[k][0] = a[0] * w0 + b[0] * frac[k];
                r[k][1] = a[1] * w0 + b[1] * frac[k];
                r[k][2] = a[2] * w0 + b[2] * frac[k];
            } else {
                sample_rare(data, u[k], v[k], l0[k], frac[k], r[k]);
            }
        }
    }

    // 6 floats out: 3 x 8B streaming stores, 8B aligned.
    float2* o = reinterpret_cast<float2*>(out + (size_t)6 * p);
    __stcs(o,     make_float2(r[0][0], r[0][1]));
    __stcs(o + 1, make_float2(r[0][2], r[1][0]));
    __stcs(o + 2, make_float2(r[1][1], r[1][2]));
}

extern "C" void kernel_launch(void* const* d_in, const int* in_sizes, int n_in,
                              void* d_out, int out_size) {
    const float* data  = (const float*)d_in[0];   // [1,4096,4096,3]
    const float4* texc2 = (const float4*)d_in[1]; // [1,1024,1024,2] as float4 pairs
    const float4* deriv = (const float4*)d_in[2]; // [1,1024,1024,4]
    float* out = (float*)d_out;                   // [1,1024,1024,3]

    (void)in_sizes; (void)n_in; (void)out_size;

    vt_downA<<<4096, 256>>>(data);
    {
        dim3 grid(16, 16);
        vt_downB<<<grid, 256>>>();
    }
    vt_sample<<<2048, 256>>>(data, texc2, deriv, out);
}

// round 15
// speedup vs baseline: 1.0718x; 1.0117x over previous
#include <cuda_runtime.h>

#define W0 4096
#define OUTW 1024
#define MAXMIP 8

// Mip texel = 4B fixed point: r[0:11) g[11:22) b[22:32)  (values in [0,1]).
// Quad entry (16B, uint4): texels {(x,y),(x+1,y),(x,y+1),(x+1,y+1)} with wrap.
// Levels 2..8: 1,398,016 entries * 16B = ~22.4MB.
__device__ uint4 g_mq[1398016];

__constant__ int MIPQ_OFF[9] = {
    0, 0,
    0,          // level 2: 1024^2
    1048576,    // level 3:  512^2
    1310720,    // level 4:  256^2
    1376256,    // level 5:  128^2
    1392640,    // level 6:   64^2
    1396736,    // level 7:   32^2
    1397760     // level 8:   16^2
};

#define OFF_L2 0
#define OFF_L3 1048576
#define OFF_L4 1310720
#define OFF_L5 1376256
#define OFF_L6 1392640
#define OFF_L7 1396736
#define OFF_L8 1397760

__device__ __forceinline__ unsigned pack_rgb(float3 v) {
    unsigned r = (unsigned)__float2int_rn(__saturatef(v.x) * 2047.0f);
    unsigned g = (unsigned)__float2int_rn(__saturatef(v.y) * 2047.0f);
    unsigned b = (unsigned)__float2int_rn(__saturatef(v.z) * 1023.0f);
    return r | (g << 11) | (b << 22);
}

__device__ __forceinline__ float3 unpack_rgb(unsigned p) {
    return make_float3((float)(p & 2047u) * (1.0f / 2047.0f),
                       (float)((p >> 11) & 2047u) * (1.0f / 2047.0f),
                       (float)(p >> 22) * (1.0f / 1023.0f));
}

// Write texel (x,y) into the 4 quad entries that reference it (w = power of 2).
__device__ __forceinline__ void store_quad(unsigned* __restrict__ base, int w,
                                           int x, int y, float3 v) {
    unsigned p = pack_rgb(v);
    int xm = (x - 1) & (w - 1);
    int ym = (y - 1) & (w - 1);
    base[((size_t)y * w + x) * 4 + 0] = p;
    base[((size_t)y * w + xm) * 4 + 1] = p;
    base[((size_t)ym * w + x) * 4 + 2] = p;
    base[((size_t)ym * w + xm) * 4 + 3] = p;
}

__device__ __forceinline__ float3 f3avg(float3 a, float3 b, float3 c, float3 d) {
    return make_float3((a.x + b.x + c.x + d.x) * 0.25f,
                       (a.y + b.y + c.y + d.y) * 0.25f,
                       (a.z + b.z + c.z + d.z) * 0.25f);
}

__device__ __forceinline__ float3 quad_avg(uint4 q) {
    return f3avg(unpack_rgb(q.x), unpack_rgb(q.y), unpack_rgb(q.z), unpack_rgb(q.w));
}

__device__ __forceinline__ float4 f4avg4(float4 a, float4 b, float4 c, float4 d) {
    return make_float4((a.x + b.x + c.x + d.x) * 0.25f,
                       (a.y + b.y + c.y + d.y) * 0.25f,
                       (a.z + b.z + c.z + d.z) * 0.25f, 0.0f);
}

// Streaming (evict-first) 3x float4 load.
__device__ __forceinline__ void load12_cs(float* r, const float4* p) {
    float4 f0 = __ldcs(p), f1 = __ldcs(p + 1), f2 = __ldcs(p + 2);
    r[0] = f0.x; r[1]  = f0.y; r[2]  = f0.z; r[3]  = f0.w;
    r[4] = f1.x; r[5]  = f1.y; r[6]  = f1.z; r[7]  = f1.w;
    r[8] = f2.x; r[9]  = f2.y; r[10] = f2.z; r[11] = f2.w;
}

// Kernel A: base (packed fp32 rgb) -> level 2 only (quad writes).
__global__ __launch_bounds__(256) void vt_downA(const float* __restrict__ data) {
    const int w2 = W0 >> 2;              // 1024
    int i = blockIdx.x * blockDim.x + threadIdx.x;
    if (i >= w2 * w2) return;

    int x2 = i & (w2 - 1);
    int y2 = i >> 10;
    const int pitch4 = 3 * w2;
    const float4* s4 = reinterpret_cast<const float4*>(data)
                       + (size_t)4 * y2 * pitch4 + 3 * x2;

    float a[12], b[12];
    float3 l1[4];

#pragma unroll
    for (int half = 0; half < 2; half++) {
        load12_cs(a, s4 + (2 * half) * pitch4);
        load12_cs(b, s4 + (2 * half + 1) * pitch4);
#pragma unroll
        for (int dx = 0; dx < 2; dx++) {
            l1[2 * half + dx] = make_float3(
                (a[6 * dx + 0] + a[6 * dx + 3] + b[6 * dx + 0] + b[6 * dx + 3]) * 0.25f,
                (a[6 * dx + 1] + a[6 * dx + 4] + b[6 * dx + 1] + b[6 * dx + 4]) * 0.25f,
                (a[6 * dx + 2] + a[6 * dx + 5] + b[6 * dx + 2] + b[6 * dx + 5]) * 0.25f);
        }
    }

    float3 l2 = f3avg(l1[0], l1[1], l1[2], l1[3]);
    store_quad(reinterpret_cast<unsigned*>(g_mq + OFF_L2), 1024, x2, y2, l2);
}

// Kernel B: level 2 -> levels 3..8 in one kernel. PDL consumer of downA.
__global__ __launch_bounds__(256) void vt_downB() {
    __shared__ float4 s4[256];
    __shared__ float4 s5[64];
    __shared__ float4 s6[16];
    __shared__ float4 s7[4];

    // Wait for downA's L2 quads before any read (PDL).
    cudaGridDependencySynchronize();

    const uint4* __restrict__ L2t = g_mq + OFF_L2;
    unsigned* __restrict__ L3 = reinterpret_cast<unsigned*>(g_mq + OFF_L3);
    unsigned* __restrict__ L4 = reinterpret_cast<unsigned*>(g_mq + OFF_L4);
    unsigned* __restrict__ L5 = reinterpret_cast<unsigned*>(g_mq + OFF_L5);
    unsigned* __restrict__ L6 = reinterpret_cast<unsigned*>(g_mq + OFF_L6);
    unsigned* __restrict__ L7 = reinterpret_cast<unsigned*>(g_mq + OFF_L7);
    unsigned* __restrict__ L8 = reinterpret_cast<unsigned*>(g_mq + OFF_L8);

    int t = threadIdx.x;
    int bx = blockIdx.x, by = blockIdx.y;
    int tx = t & 15, ty = t >> 4;

    {
        int x0 = 64 * bx + 4 * tx;
        int y0 = 64 * by + 4 * ty;
        const uint4* src = L2t + (size_t)y0 * 1024 + x0;

        float3 l3[4];
        l3[0] = quad_avg(src[0]);
        l3[1] = quad_avg(src[2]);
        l3[2] = quad_avg(src[(size_t)2 * 1024]);
        l3[3] = quad_avg(src[(size_t)2 * 1024 + 2]);

        int x3 = 32 * bx + 2 * tx;
        int y3 = 32 * by + 2 * ty;
        store_quad(L3, 512, x3,     y3,     l3[0]);
        store_quad(L3, 512, x3 + 1, y3,     l3[1]);
        store_quad(L3, 512, x3,     y3 + 1, l3[2]);
        store_quad(L3, 512, x3 + 1, y3 + 1, l3[3]);

        float3 l4 = f3avg(l3[0], l3[1], l3[2], l3[3]);
        store_quad(L4, 256, 16 * bx + tx, 16 * by + ty, l4);
        s4[ty * 16 + tx] = make_float4(l4.x, l4.y, l4.z, 0.0f);
    }
    __syncthreads();

    if (t < 64) {
        int x = t & 7, y = t >> 3;
        float4 v = f4avg4(s4[(2 * y) * 16 + 2 * x],     s4[(2 * y) * 16 + 2 * x + 1],
                          s4[(2 * y + 1) * 16 + 2 * x], s4[(2 * y + 1) * 16 + 2 * x + 1]);
        store_quad(L5, 128, 8 * bx + x, 8 * by + y, make_float3(v.x, v.y, v.z));
        s5[y * 8 + x] = v;
    }
    __syncthreads();

    if (t < 16) {
        int x = t & 3, y = t >> 2;
        float4 v = f4avg4(s5[(2 * y) * 8 + 2 * x],     s5[(2 * y) * 8 + 2 * x + 1],
                          s5[(2 * y + 1) * 8 + 2 * x], s5[(2 * y + 1) * 8 + 2 * x + 1]);
        store_quad(L6, 64, 4 * bx + x, 4 * by + y, make_float3(v.x, v.y, v.z));
        s6[y * 4 + x] = v;
    }
    __syncthreads();

    if (t < 4) {
        int x = t & 1, y = t >> 1;
        float4 v = f4avg4(s6[(2 * y) * 4 + 2 * x],     s6[(2 * y) * 4 + 2 * x + 1],
                          s6[(2 * y + 1) * 4 + 2 * x], s6[(2 * y + 1) * 4 + 2 * x + 1]);
        store_quad(L7, 32, 2 * bx + x, 2 * by + y, make_float3(v.x, v.y, v.z));
        s7[y * 2 + x] = v;
    }
    __syncthreads();

    if (t == 0) {
        float4 a = s7[0], b = s7[1], c = s7[2], d = s7[3];
        store_quad(L8, 16, bx, by,
                   make_float3((a.x + b.x + c.x + d.x) * 0.25f,
                               (a.y + b.y + c.y + d.y) * 0.25f,
                               (a.z + b.z + c.z + d.z) * 0.25f));
    }
}

// ---------- sampling helpers ----------

__device__ __forceinline__ void wrap_setup(float u, float v, int w,
                                           int& x0, int& y0, int& x1, int& y1,
                                           float& fx, float& fy) {
    float x = u * (float)w - 0.5f;
    float y = v * (float)w - 0.5f;
    float x0f = floorf(x);
    float y0f = floorf(y);
    fx = x - x0f;
    fy = y - y0f;
    x0 = (int)x0f;
    y0 = (int)y0f;
    if (x0 < 0) x0 += w;
    if (y0 < 0) y0 += w;
    x1 = x0 + 1; if (x1 == w) x1 = 0;
    y1 = y0 + 1; if (y1 == w) y1 = 0;
}

__device__ __forceinline__ void quad_blend(uint4 e, float fx, float fy, float rgb[3]) {
    float3 t00 = unpack_rgb(e.x), t01 = unpack_rgb(e.y);
    float3 t10 = unpack_rgb(e.z), t11 = unpack_rgb(e.w);
    float w00 = (1.0f - fx) * (1.0f - fy);
    float w01 = fx * (1.0f - fy);
    float w10 = (1.0f - fx) * fy;
    float w11 = fx * fy;
    rgb[0] = t00.x * w00 + t01.x * w01 + t10.x * w10 + t11.x * w11;
    rgb[1] = t00.y * w00 + t01.y * w01 + t10.y * w10 + t11.y * w11;
    rgb[2] = t00.z * w00 + t01.z * w01 + t10.z * w10 + t11.z * w11;
}

// Quad entry address for (u,v) at level lvl (>=2). fx/fy out.
__device__ __forceinline__ const uint4* quad_addr(int lvl, float u, float v,
                                                  float& fx, float& fy) {
    int w = W0 >> lvl;
    float x = u * (float)w - 0.5f;
    float y = v * (float)w - 0.5f;
    float xf = floorf(x), yf = floorf(y);
    int xi = (int)xf, yi = (int)yf;
    if (xi < 0) xi += w;
    if (yi < 0) yi += w;
    fx = x - xf; fy = y - yf;
    return g_mq + MIPQ_OFF[lvl] + (size_t)yi * w + xi;
}

// Exact fp32 bilinear on base (level 0). Rare path.
__device__ __forceinline__ void vt_bilinear0(const float* __restrict__ tex,
                                             float u, float v, float rgb[3]) {
    int x0, y0, x1, y1; float fx, fy;
    wrap_setup(u, v, W0, x0, y0, x1, y1, fx, fy);

    const float* p00 = tex + ((size_t)y0 * W0 + x0) * 3;
    const float* p01 = tex + ((size_t)y0 * W0 + x1) * 3;
    const float* p10 = tex + ((size_t)y1 * W0 + x0) * 3;
    const float* p11 = tex + ((size_t)y1 * W0 + x1) * 3;

    float w00 = (1.0f - fx) * (1.0f - fy);
    float w01 = fx * (1.0f - fy);
    float w10 = (1.0f - fx) * fy;
    float w11 = fx * fy;

#pragma unroll
    for (int c = 0; c < 3; c++)
        rgb[c] = p00[c] * w00 + p01[c] * w01 + p10[c] * w10 + p11[c] * w11;
}

__device__ __forceinline__ float3 l1_texel(const float* __restrict__ base,
                                           int lx, int ly) {
    const float2* r0 = reinterpret_cast<const float2*>(
        base + ((size_t)(2 * ly) * W0 + 2 * lx) * 3);
    const float2* r1 = reinterpret_cast<const float2*>(
        base + ((size_t)(2 * ly + 1) * W0 + 2 * lx) * 3);
    float2 a0 = r0[0], a1 = r0[1], a2 = r0[2];
    float2 b0 = r1[0], b1 = r1[1], b2 = r1[2];
    return make_float3((a0.x + a1.y + b0.x + b1.y) * 0.25f,
                       (a0.y + a2.x + b0.y + b2.x) * 0.25f,
                       (a1.x + a2.y + b1.x + b2.y) * 0.25f);
}

__device__ __forceinline__ void vt_bilinear_l1(const float* __restrict__ tex,
                                               float u, float v, float rgb[3]) {
    const int w1 = W0 >> 1;
    int x0, y0, x1, y1; float fx, fy;
    wrap_setup(u, v, w1, x0, y0, x1, y1, fx, fy);

    float3 t00 = l1_texel(tex, x0, y0);
    float3 t01 = l1_texel(tex, x1, y0);
    float3 t10 = l1_texel(tex, x0, y1);
    float3 t11 = l1_texel(tex, x1, y1);

    float w00 = (1.0f - fx) * (1.0f - fy);
    float w01 = fx * (1.0f - fy);
    float w10 = (1.0f - fx) * fy;
    float w11 = fx * fy;

    rgb[0] = t00.x * w00 + t01.x * w01 + t10.x * w10 + t11.x * w11;
    rgb[1] = t00.y * w00 + t01.y * w01 + t10.y * w10 + t11.y * w11;
    rgb[2] = t00.z * w00 + t01.z * w01 + t10.z * w10 + t11.z * w11;
}

// Rare path (l0 < 2): exact fp32 from base.
__device__ __noinline__ void sample_rare(const float* __restrict__ data,
                                         float u, float v, int l0, float frac,
                                         float rgb[3]) {
    float a[3], b[3];
    if (l0 == 1) {
        vt_bilinear_l1(data, u, v, a);
        float fx, fy;
        const uint4* e = quad_addr(2, u, v, fx, fy);
        quad_blend(*e, fx, fy, b);
    } else {
        vt_bilinear0(data, u, v, a);
        vt_bilinear_l1(data, u, v, b);
    }
    float w0 = 1.0f - frac;
    rgb[0] = a[0] * w0 + b[0] * frac;
    rgb[1] = a[1] * w0 + b[1] * frac;
    rgb[2] = a[2] * w0 + b[2] * frac;
}

// Two pixels per thread. PDL consumer: prologue (texc/deriv loads + lod math)
// overlaps downB; grid-dependency sync only before the first mip dereference.
__global__ __launch_bounds__(256) void vt_sample(const float* __restrict__ data,
                          const float4* __restrict__ texc2,
                          const float4* __restrict__ deriv,
                          float* __restrict__ out) {
    int p = blockIdx.x * blockDim.x + threadIdx.x;
    const int npairs = OUTW * OUTW / 2;
    if (p >= npairs) {
        cudaGridDependencySynchronize();
        return;
    }

    float4 uvs = __ldcs(texc2 + p);        // (u0,v0,u1,v1)
    float4 dA = __ldcs(deriv + 2 * p);
    float4 dB = __ldcs(deriv + 2 * p + 1);

    float u[2] = { uvs.x, uvs.z };
    float v[2] = { uvs.y, uvs.w };
    float4 dd[2] = { dA, dB };

    float frac[2];
    int l0[2], l1v[2];
    bool rare = false;
#pragma unroll
    for (int k = 0; k < 2; k++) {
        float dudx = dd[k].x * (float)W0;
        float dvdx = dd[k].y * (float)W0;
        float dudy = dd[k].z * (float)W0;
        float dvdy = dd[k].w * (float)W0;
        float rho2 = fmaxf(dudx * dudx + dvdx * dvdx, dudy * dudy + dvdy * dvdy);
        float lod = 0.5f * __log2f(fmaxf(rho2, 1e-20f));
        lod = fminf(fmaxf(lod, 0.0f), (float)MAXMIP);
        int l = (int)lod;
        if (l > MAXMIP) l = MAXMIP;
        l0[k] = l;
        frac[k] = lod - (float)l;
        l1v[k] = (l < MAXMIP) ? (l + 1) : MAXMIP;
        rare |= (l < 2);
    }

    float r[2][3];

    if (!rare) {
        // Addresses are mip-independent; compute before the dependency sync.
        float fx0[2], fy0[2], fx1[2], fy1[2];
        const uint4* a0 = quad_addr(l0[0],  u[0], v[0], fx0[0], fy0[0]);
        const uint4* a1 = quad_addr(l1v[0], u[0], v[0], fx1[0], fy1[0]);
        const uint4* b0 = quad_addr(l0[1],  u[1], v[1], fx0[1], fy0[1]);
        const uint4* b1 = quad_addr(l1v[1], u[1], v[1], fx1[1], fy1[1]);

        // Wait for downB's mip writes, then issue all 4 LDG.128.
        cudaGridDependencySynchronize();

        uint4 eA0 = *a0;
        uint4 eA1 = *a1;
        uint4 eB0 = *b0;
        uint4 eB1 = *b1;

        float a[3], b[3];
        quad_blend(eA0, fx0[0], fy0[0], a);
        quad_blend(eA1, fx1[0], fy1[0], b);
        float w0 = 1.0f - frac[0];
        r[0][0] = a[0] * w0 + b[0] * frac[0];
        r[0][1] = a[1] * w0 + b[1] * frac[0];
        r[0][2] = a[2] * w0 + b[2] * frac[0];

        quad_blend(eB0, fx0[1], fy0[1], a);
        quad_blend(eB1, fx1[1], fy1[1], b);
        float w1 = 1.0f - frac[1];
        r[1][0] = a[0] * w1 + b[0] * frac[1];
        r[1][1] = a[1] * w1 + b[1] * frac[1];
        r[1][2] = a[2] * w1 + b[2] * frac[1];
    } else {
        cudaGridDependencySynchronize();
#pragma unroll
        for (int k = 0; k < 2; k++) {
            if (l0[k] >= 2) {
                float fxa, fya, fxb, fyb;
                const uint4* qa = quad_addr(l0[k],  u[k], v[k], fxa, fya);
                const uint4* qb = quad_addr(l1v[k], u[k], v[k], fxb, fyb);
                uint4 ea = *qa;
                uint4 eb = *qb;
                float a[3], b[3];
                quad_blend(ea, fxa, fya, a);
                quad_blend(eb, fxb, fyb, b);
                float w0 = 1.0f - frac[k];
                r[k][0] = a[0] * w0 + b[0] * frac[k];
                r[k][1] = a[1] * w0 + b[1] * frac[k];
                r[k][2] = a[2] * w0 + b[2] * frac[k];
            } else {
                sample_rare(data, u[k], v[k], l0[k], frac[k], r[k]);
            }
        }
    }

    // 6 floats out: 3 x 8B streaming stores, 8B aligned.
    float2* o = reinterpret_cast<float2*>(out + (size_t)6 * p);
    __stcs(o,     make_float2(r[0][0], r[0][1]));
    __stcs(o + 1, make_float2(r[0][2], r[1][0]));
    __stcs(o + 2, make_float2(r[1][1], r[1][2]));
}

extern "C" void kernel_launch(void* const* d_in, const int* in_sizes, int n_in,
                              void* d_out, int out_size) {
    const float* data  = (const float*)d_in[0];   // [1,4096,4096,3]
    const float4* texc2 = (const float4*)d_in[1]; // [1,1024,1024,2] as float4 pairs
    const float4* deriv = (const float4*)d_in[2]; // [1,1024,1024,4]
    float* out = (float*)d_out;                   // [1,1024,1024,3]

    (void)in_sizes; (void)n_in; (void)out_size;

    // A: base -> L2 (plain launch)
    vt_downA<<<4096, 256>>>(data);

    // B: L2 -> L3..L8, PDL after A (launch overlaps A's tail; syncs at entry)
    {
        cudaLaunchConfig_t cfg = {};
        cfg.gridDim = dim3(16, 16, 1);
        cfg.blockDim = dim3(256, 1, 1);
        cudaLaunchAttribute attr[1];
        attr[0].id = cudaLaunchAttributeProgrammaticStreamSerialization;
        attr[0].val.programmaticStreamSerializationAllowed = 1;
        cfg.attrs = attr;
        cfg.numAttrs = 1;
        cudaLaunchKernelEx(&cfg, vt_downB);
    }

    // Sample: PDL after B (prologue overlaps B; syncs before mip reads)
    {
        cudaLaunchConfig_t cfg = {};
        cfg.gridDim = dim3(2048, 1, 1);
        cfg.blockDim = dim3(256, 1, 1);
        cudaLaunchAttribute attr[1];
        attr[0].id = cudaLaunchAttributeProgrammaticStreamSerialization;
        attr[0].val.programmaticStreamSerializationAllowed = 1;
        cfg.attrs = attr;
        cfg.numAttrs = 1;
        cudaLaunchKernelEx(&cfg, vt_sample, data, texc2, deriv, out);
    }
}